// round 2
// baseline (speedup 1.0000x reference)
#include <cuda_runtime.h>

#define DD 128
#define TE 32
#define STR 34   // padded row stride (even -> 8B aligned float2, conflict-free)

// 50000 nodes * 128 features scratch for segment-sum aggregation
__device__ float g_agg[50000 * 128];
__device__ int g_is64;

__device__ __forceinline__ unsigned long long pack2f(float lo, float hi) {
    unsigned long long r;
    asm("mov.b64 %0, {%1,%2};" : "=l"(r) : "f"(lo), "f"(hi));
    return r;
}
__device__ __forceinline__ void unpack2f(unsigned long long v, float& lo, float& hi) {
    asm("mov.b64 {%0,%1}, %2;" : "=f"(lo), "=f"(hi) : "l"(v));
}
__device__ __forceinline__ unsigned long long fma2(unsigned long long a, unsigned long long b, unsigned long long c) {
    unsigned long long d;
    asm("fma.rn.f32x2 %0, %1, %2, %3;" : "=l"(d) : "l"(a), "l"(b), "l"(c));
    return d;
}
__device__ __forceinline__ float silu_f(float x) {
    return __fdividef(x, 1.0f + __expf(-x));
}

// Column-GEMM: out[e] = sum_k sIn[k][e] * W[k][j], thread owns column j.
// sIn is [K][TE] with row stride STR floats. Weights prefetched 8 ahead.
template<int K>
__device__ __forceinline__ void mm_col(const float* sIn, const float* __restrict__ W,
                                       int j, float out[TE]) {
    unsigned long long acc[TE / 2];
#pragma unroll
    for (int p = 0; p < TE / 2; p++) acc[p] = 0ull;

    constexpr int PF = 8;
    float w[PF];
#pragma unroll
    for (int i = 0; i < PF; i++) w[i] = (i < K) ? W[i * DD + j] : 0.0f;

    constexpr int KMAIN = (K / PF) * PF;
#pragma unroll 1
    for (int kb = 0; kb < KMAIN; kb += PF) {
        float wn[PF];
#pragma unroll
        for (int i = 0; i < PF; i++) {
            int kk = kb + PF + i;
            wn[i] = (kk < K) ? W[kk * DD + j] : 0.0f;
        }
#pragma unroll
        for (int i = 0; i < PF; i++) {
            unsigned long long ww = pack2f(w[i], w[i]);
            const unsigned long long* arow =
                reinterpret_cast<const unsigned long long*>(sIn + (kb + i) * STR);
#pragma unroll
            for (int p = 0; p < TE / 2; p++) acc[p] = fma2(arow[p], ww, acc[p]);
        }
#pragma unroll
        for (int i = 0; i < PF; i++) w[i] = wn[i];
    }
    // tail (K=257 -> one leftover k, weight already prefetched in w[0])
#pragma unroll
    for (int k = KMAIN; k < K; k++) {
        unsigned long long ww = pack2f(w[k - KMAIN], w[k - KMAIN]);
        const unsigned long long* arow =
            reinterpret_cast<const unsigned long long*>(sIn + k * STR);
#pragma unroll
        for (int p = 0; p < TE / 2; p++) acc[p] = fma2(arow[p], ww, acc[p]);
    }
#pragma unroll
    for (int p = 0; p < TE / 2; p++) unpack2f(acc[p], out[2 * p], out[2 * p + 1]);
}

// smem float offsets (edge kernel)
#define OFF_SA   0
#define OFF_ST   8740                 // 257*34=8738 rounded up to even
#define OFF_SM   (OFF_ST + DD * STR)  // 13092
#define OFF_SC   (OFF_SM + DD * STR)  // 17444
#define OFF_WC2  (OFF_SC + DD * STR)  // 21796
#define OFF_DX   (OFF_WC2 + DD)       // 21924
#define OFF_DY   (OFF_DX + TE)
#define OFF_DZ   (OFF_DY + TE)
#define OFF_ID   (OFF_DZ + TE)
#define OFF_ROW  (OFF_ID + TE)        // 22052 (ints)
#define OFF_COL  (OFF_ROW + TE)
#define EDGE_SMEM_BYTES ((OFF_COL + TE) * 4)   // 88464

// Probe edge_index dtype: int64 little-endian values < 50000 have all odd
// 32-bit words zero; int32 data does not (w.p. ~1). Deterministic.
__global__ void egnn_detect_kernel(const int* __restrict__ ei32) {
    int is64 = 1;
#pragma unroll
    for (int i = 1; i < 64; i += 2)
        if (ei32[i] != 0) is64 = 0;
    g_is64 = is64;
}

__global__ __launch_bounds__(128, 2) void egnn_edge_kernel(
    const float* __restrict__ h, const float* __restrict__ pos,
    const int* __restrict__ ei32, long long E,
    const float* __restrict__ We1, const float* __restrict__ be1,
    const float* __restrict__ We2, const float* __restrict__ be2,
    const float* __restrict__ Wc1, const float* __restrict__ bc1,
    const float* __restrict__ Wc2, float* __restrict__ pos_out)
{
    extern __shared__ float smem[];
    float* sA   = smem + OFF_SA;   // edge_input transposed [257][TE]
    float* sT   = smem + OFF_ST;   // t1  [128][TE]
    float* sM   = smem + OFF_SM;   // msg [128][TE]
    float* sC   = smem + OFF_SC;   // coord-mlp hidden [128][TE]
    float* sWc2 = smem + OFF_WC2;
    float* sdx  = smem + OFF_DX;
    float* sdy  = smem + OFF_DY;
    float* sdz  = smem + OFF_DZ;
    float* sid  = smem + OFF_ID;
    int*   srow = (int*)(smem + OFF_ROW);
    int*   scol = (int*)(smem + OFF_COL);

    const int tid = threadIdx.x;
    const long long e0 = (long long)blockIdx.x * TE;

    sWc2[tid] = Wc2[tid];
    if (tid < TE) {
        long long e = e0 + tid;
        if (e >= E) e = E - 1;
        int r, c;
        if (g_is64) {
            r = ei32[2 * e];
            c = ei32[2 * (E + e)];
        } else {
            r = ei32[e];
            c = ei32[E + e];
        }
        srow[tid] = r;
        scol[tid] = c;
        float dx = pos[r * 3 + 0] - pos[c * 3 + 0];
        float dy = pos[r * 3 + 1] - pos[c * 3 + 1];
        float dz = pos[r * 3 + 2] - pos[c * 3 + 2];
        float d = sqrtf(dx * dx + dy * dy + dz * dz);
        d = fmaxf(d, 1e-6f);
        sA[256 * STR + tid] = d;      // dist feature (row 256)
        sdx[tid] = dx; sdy[tid] = dy; sdz[tid] = dz;
        sid[tid] = 1.0f / d;
    }
    __syncthreads();

    // gather h[row] -> rows 0..127, h[col] -> rows 128..255 (transposed)
#pragma unroll 4
    for (int e = 0; e < TE; e++) {
        long long r = srow[e];
        long long c = scol[e];
        sA[tid * STR + e]        = h[r * DD + tid];
        sA[(DD + tid) * STR + e] = h[c * DD + tid];
    }
    __syncthreads();

    float v[TE];
    mm_col<2 * DD + 1>(sA, We1, tid, v);
    {
        float bj = be1[tid];
#pragma unroll
        for (int e = 0; e < TE; e++) sT[tid * STR + e] = silu_f(v[e] + bj);
    }
    __syncthreads();

    mm_col<DD>(sT, We2, tid, v);
    {
        float bj = be2[tid];
#pragma unroll
        for (int e = 0; e < TE; e++) sM[tid * STR + e] = silu_f(v[e] + bj);
    }
    __syncthreads();

    mm_col<DD>(sM, Wc1, tid, v);
    {
        float bj = bc1[tid];
#pragma unroll
        for (int e = 0; e < TE; e++) sC[tid * STR + e] = silu_f(v[e] + bj);
    }
    __syncthreads();

    // coord weight: cw[e] = clip(sum_j sC[j][e] * Wc2[j], -1, 1); pos scatter
    if (tid < TE && e0 + tid < E) {
        const int e = tid;
        float s = 0.f;
#pragma unroll 16
        for (int j = 0; j < DD; j++) s += sC[j * STR + e] * sWc2[j];
        s = fminf(fmaxf(s, -1.0f), 1.0f);
        float f = s * sid[e];
        long long r = srow[e];
        atomicAdd(&pos_out[r * 3 + 0], sdx[e] * f);
        atomicAdd(&pos_out[r * 3 + 1], sdy[e] * f);
        atomicAdd(&pos_out[r * 3 + 2], sdz[e] * f);
    }

    // agg[row] += msg  (coalesced across the 128 threads for each edge)
#pragma unroll 4
    for (int e = 0; e < TE; e++) {
        if (e0 + e < E) {
            long long r = srow[e];
            atomicAdd(&g_agg[r * DD + tid], sM[tid * STR + e]);
        }
    }
}

#define NODE_SMEM_BYTES ((256 * STR + DD * STR) * 4)   // 52224

__global__ __launch_bounds__(128, 2) void egnn_node_kernel(
    const float* __restrict__ h,
    const float* __restrict__ Wn1, const float* __restrict__ bn1,
    const float* __restrict__ Wn2, const float* __restrict__ bn2,
    float* __restrict__ h_out, int N)
{
    extern __shared__ float smem[];
    float* sA = smem;                 // [256][TE] = [h ; agg] transposed
    float* sT = smem + 256 * STR;     // [128][TE]

    const int tid = threadIdx.x;
    const long long n0 = (long long)blockIdx.x * TE;

#pragma unroll 4
    for (int e = 0; e < TE; e++) {
        long long n = n0 + e;
        if (n >= N) n = N - 1;
        sA[tid * STR + e]        = h[n * DD + tid];
        sA[(DD + tid) * STR + e] = g_agg[n * DD + tid];
    }
    __syncthreads();

    float v[TE];
    mm_col<2 * DD>(sA, Wn1, tid, v);
    {
        float bj = bn1[tid];
#pragma unroll
        for (int e = 0; e < TE; e++) sT[tid * STR + e] = silu_f(v[e] + bj);
    }
    __syncthreads();

    mm_col<DD>(sT, Wn2, tid, v);
    float bj = bn2[tid];
#pragma unroll
    for (int e = 0; e < TE; e++) {
        long long n = n0 + e;
        if (n < N) h_out[n * DD + tid] = h[n * DD + tid] + v[e] + bj;
    }
}

__global__ void egnn_init_kernel(const float* __restrict__ pos,
                                 float* __restrict__ pos_out,
                                 long long nAgg, long long nPos)
{
    long long i = (long long)blockIdx.x * blockDim.x + threadIdx.x;
    if (i < nAgg) g_agg[i] = 0.0f;
    if (i < nPos) pos_out[i] = pos[i];
}

extern "C" void kernel_launch(void* const* d_in, const int* in_sizes, int n_in,
                              void* d_out, int out_size)
{
    const float* h   = (const float*)d_in[0];
    const float* pos = (const float*)d_in[1];
    const int*   ei  = (const int*)d_in[2];   // dtype probed on device (int32 vs int64)
    const float* We1 = (const float*)d_in[3];
    const float* be1 = (const float*)d_in[4];
    const float* We2 = (const float*)d_in[5];
    const float* be2 = (const float*)d_in[6];
    const float* Wn1 = (const float*)d_in[7];
    const float* bn1 = (const float*)d_in[8];
    const float* Wn2 = (const float*)d_in[9];
    const float* bn2 = (const float*)d_in[10];
    const float* Wc1 = (const float*)d_in[11];
    const float* bc1 = (const float*)d_in[12];
    const float* Wc2 = (const float*)d_in[13];

    const int N = in_sizes[0] / DD;
    const long long E = (long long)in_sizes[2] / 2;

    float* h_out   = (float*)d_out;
    float* pos_out = h_out + (long long)N * DD;

    cudaFuncSetAttribute(egnn_edge_kernel, cudaFuncAttributeMaxDynamicSharedMemorySize, EDGE_SMEM_BYTES);
    cudaFuncSetAttribute(egnn_node_kernel, cudaFuncAttributeMaxDynamicSharedMemorySize, NODE_SMEM_BYTES);

    egnn_detect_kernel<<<1, 1>>>(ei);

    long long nAgg = (long long)N * DD;
    long long nPos = (long long)N * 3;
    int ib = (int)((nAgg + 255) / 256);
    egnn_init_kernel<<<ib, 256>>>(pos, pos_out, nAgg, nPos);

    int eb = (int)((E + TE - 1) / TE);
    egnn_edge_kernel<<<eb, 128, EDGE_SMEM_BYTES>>>(
        h, pos, ei, E, We1, be1, We2, be2, Wc1, bc1, Wc2, pos_out);

    int nb = (N + TE - 1) / TE;
    egnn_node_kernel<<<nb, 128, NODE_SMEM_BYTES>>>(
        h, Wn1, bn1, Wn2, bn2, h_out, N);
}

// round 3
// speedup vs baseline: 1.0960x; 1.0960x over previous
#include <cuda_runtime.h>

#define DD 128
#define TE 32      // edges (or nodes) per block
#define EH 16      // edges per thread-half
#define STR 36     // row stride in floats: multiple of 4 -> 16B-aligned rows

__device__ float g_agg[50000 * 128];
__device__ int g_is64;

__device__ __forceinline__ unsigned long long pack2f(float lo, float hi) {
    unsigned long long r;
    asm("mov.b64 %0, {%1,%2};" : "=l"(r) : "f"(lo), "f"(hi));
    return r;
}
__device__ __forceinline__ void unpack2f(unsigned long long v, float& lo, float& hi) {
    asm("mov.b64 {%0,%1}, %2;" : "=f"(lo), "=f"(hi) : "l"(v));
}
__device__ __forceinline__ unsigned long long fma2(unsigned long long a, unsigned long long b, unsigned long long c) {
    unsigned long long d;
    asm("fma.rn.f32x2 %0, %1, %2, %3;" : "=l"(d) : "l"(a), "l"(b), "l"(c));
    return d;
}
__device__ __forceinline__ float silu_f(float x) {
    return __fdividef(x, 1.0f + __expf(-x));
}

// out[e] = sum_k sIn[k*STR + e] * W[k*DD + j] for e in 0..15.
// sIn must be pre-offset to this thread's 16-edge half (16B aligned).
template<int K>
__device__ __forceinline__ void mm_col16(const float* sIn, const float* __restrict__ W,
                                         int j, float out[EH]) {
    unsigned long long acc[EH / 2];
#pragma unroll
    for (int p = 0; p < EH / 2; p++) acc[p] = 0ull;

    constexpr int PF = 4;
    float w[PF];
#pragma unroll
    for (int i = 0; i < PF; i++) w[i] = (i < K) ? W[i * DD + j] : 0.0f;

    constexpr int KMAIN = (K / PF) * PF;
#pragma unroll 1
    for (int kb = 0; kb < KMAIN; kb += PF) {
        float wn[PF];
#pragma unroll
        for (int i = 0; i < PF; i++) {
            int kk = kb + PF + i;
            wn[i] = (kk < K) ? W[kk * DD + j] : 0.0f;
        }
#pragma unroll
        for (int i = 0; i < PF; i++) {
            unsigned long long ww = pack2f(w[i], w[i]);
            const ulonglong2* a2 = reinterpret_cast<const ulonglong2*>(sIn + (kb + i) * STR);
            ulonglong2 q0 = a2[0];
            ulonglong2 q1 = a2[1];
            ulonglong2 q2 = a2[2];
            ulonglong2 q3 = a2[3];
            acc[0] = fma2(q0.x, ww, acc[0]);
            acc[1] = fma2(q0.y, ww, acc[1]);
            acc[2] = fma2(q1.x, ww, acc[2]);
            acc[3] = fma2(q1.y, ww, acc[3]);
            acc[4] = fma2(q2.x, ww, acc[4]);
            acc[5] = fma2(q2.y, ww, acc[5]);
            acc[6] = fma2(q3.x, ww, acc[6]);
            acc[7] = fma2(q3.y, ww, acc[7]);
        }
#pragma unroll
        for (int i = 0; i < PF; i++) w[i] = wn[i];
    }
#pragma unroll
    for (int k = KMAIN; k < K; k++) {   // tail (K=257 -> one k)
        unsigned long long ww = pack2f(w[k - KMAIN], w[k - KMAIN]);
        const ulonglong2* a2 = reinterpret_cast<const ulonglong2*>(sIn + k * STR);
        ulonglong2 q0 = a2[0];
        ulonglong2 q1 = a2[1];
        ulonglong2 q2 = a2[2];
        ulonglong2 q3 = a2[3];
        acc[0] = fma2(q0.x, ww, acc[0]);
        acc[1] = fma2(q0.y, ww, acc[1]);
        acc[2] = fma2(q1.x, ww, acc[2]);
        acc[3] = fma2(q1.y, ww, acc[3]);
        acc[4] = fma2(q2.x, ww, acc[4]);
        acc[5] = fma2(q2.y, ww, acc[5]);
        acc[6] = fma2(q3.x, ww, acc[6]);
        acc[7] = fma2(q3.y, ww, acc[7]);
    }
#pragma unroll
    for (int p = 0; p < EH / 2; p++) unpack2f(acc[p], out[2 * p], out[2 * p + 1]);
}

// smem float offsets (edge kernel); sM overlays sA, sC overlays sT
#define OFF_SA   0
#define OFF_ST   (257 * STR)          // 9252
#define OFF_WC2  (OFF_ST + DD * STR)  // 13860
#define OFF_DX   (OFF_WC2 + DD)
#define OFF_DY   (OFF_DX + TE)
#define OFF_DZ   (OFF_DY + TE)
#define OFF_ID   (OFF_DZ + TE)
#define OFF_ROW  (OFF_ID + TE)
#define OFF_COL  (OFF_ROW + TE)
#define EDGE_SMEM_BYTES ((OFF_COL + TE) * 4)   // 56720

__global__ void egnn_detect_kernel(const int* __restrict__ ei32) {
    int is64 = 1;
#pragma unroll
    for (int i = 1; i < 64; i += 2)
        if (ei32[i] != 0) is64 = 0;
    g_is64 = is64;
}

__global__ __launch_bounds__(256, 3) void egnn_edge_kernel(
    const float* __restrict__ h, const float* __restrict__ pos,
    const int* __restrict__ ei32, long long E,
    const float* __restrict__ We1, const float* __restrict__ be1,
    const float* __restrict__ We2, const float* __restrict__ be2,
    const float* __restrict__ Wc1, const float* __restrict__ bc1,
    const float* __restrict__ Wc2, float* __restrict__ pos_out)
{
    extern __shared__ __align__(16) float smem[];
    float* sA   = smem + OFF_SA;   // [257][STR]; sM (msg) overlays this after layer 1
    float* sT   = smem + OFF_ST;   // [128][STR]; sC overlays this after layer 2
    float* sM   = sA;
    float* sC   = sT;
    float* sWc2 = smem + OFF_WC2;
    float* sdx  = smem + OFF_DX;
    float* sdy  = smem + OFF_DY;
    float* sdz  = smem + OFF_DZ;
    float* sid  = smem + OFF_ID;
    int*   srow = (int*)(smem + OFF_ROW);
    int*   scol = (int*)(smem + OFF_COL);

    const int t  = threadIdx.x;
    const int j  = t & 127;
    const int hf = t >> 7;          // 0 or 1: which 16-edge half
    const long long e0 = (long long)blockIdx.x * TE;

    if (t < DD) sWc2[t] = Wc2[t];
    if (t < TE) {
        long long e = e0 + t;
        if (e >= E) e = E - 1;
        int r, c;
        if (g_is64) { r = ei32[2 * e]; c = ei32[2 * (E + e)]; }
        else        { r = ei32[e];     c = ei32[E + e]; }
        srow[t] = r;
        scol[t] = c;
        float dx = pos[r * 3 + 0] - pos[c * 3 + 0];
        float dy = pos[r * 3 + 1] - pos[c * 3 + 1];
        float dz = pos[r * 3 + 2] - pos[c * 3 + 2];
        float d = sqrtf(dx * dx + dy * dy + dz * dz);
        d = fmaxf(d, 1e-6f);
        sA[256 * STR + t] = d;
        sdx[t] = dx; sdy[t] = dy; sdz[t] = dz;
        sid[t] = 1.0f / d;
    }
    __syncthreads();

    // gather h[row] -> rows 0..127, h[col] -> rows 128..255 (transposed)
#pragma unroll 4
    for (int e2 = 0; e2 < EH; e2++) {
        int e = hf * EH + e2;
        long long r = srow[e];
        long long c = scol[e];
        sA[j * STR + e]        = h[r * DD + j];
        sA[(DD + j) * STR + e] = h[c * DD + j];
    }
    __syncthreads();

    const float* sInH = nullptr;   // silence unused warnings pattern
    (void)sInH;
    float v[EH];

    // layer 1: [257] -> [128], SiLU
    mm_col16<2 * DD + 1>(sA + hf * EH, We1, j, v);
    {
        float bj = be1[j];
        float* dst = sT + j * STR + hf * EH;
#pragma unroll
        for (int g = 0; g < EH / 4; g++) {
            float4 f;
            f.x = silu_f(v[4 * g + 0] + bj);
            f.y = silu_f(v[4 * g + 1] + bj);
            f.z = silu_f(v[4 * g + 2] + bj);
            f.w = silu_f(v[4 * g + 3] + bj);
            *reinterpret_cast<float4*>(dst + 4 * g) = f;
        }
    }
    __syncthreads();

    // layer 2: [128] -> msg [128], SiLU (writes overlay sA)
    mm_col16<DD>(sT + hf * EH, We2, j, v);
    {
        float bj = be2[j];
        float* dst = sM + j * STR + hf * EH;
#pragma unroll
        for (int g = 0; g < EH / 4; g++) {
            float4 f;
            f.x = silu_f(v[4 * g + 0] + bj);
            f.y = silu_f(v[4 * g + 1] + bj);
            f.z = silu_f(v[4 * g + 2] + bj);
            f.w = silu_f(v[4 * g + 3] + bj);
            *reinterpret_cast<float4*>(dst + 4 * g) = f;
        }
    }
    __syncthreads();

    // layer 3 (coord MLP hidden): msg -> [128], SiLU (writes overlay sT)
    mm_col16<DD>(sM + hf * EH, Wc1, j, v);
    {
        float bj = bc1[j];
        float* dst = sC + j * STR + hf * EH;
#pragma unroll
        for (int g = 0; g < EH / 4; g++) {
            float4 f;
            f.x = silu_f(v[4 * g + 0] + bj);
            f.y = silu_f(v[4 * g + 1] + bj);
            f.z = silu_f(v[4 * g + 2] + bj);
            f.w = silu_f(v[4 * g + 3] + bj);
            *reinterpret_cast<float4*>(dst + 4 * g) = f;
        }
    }
    __syncthreads();

    // coord weight + pos scatter
    if (t < TE && e0 + t < E) {
        const int e = t;
        float s = 0.f;
#pragma unroll 16
        for (int jj = 0; jj < DD; jj++) s += sC[jj * STR + e] * sWc2[jj];
        s = fminf(fmaxf(s, -1.0f), 1.0f);
        float f = s * sid[e];
        long long r = srow[e];
        atomicAdd(&pos_out[r * 3 + 0], sdx[e] * f);
        atomicAdd(&pos_out[r * 3 + 1], sdy[e] * f);
        atomicAdd(&pos_out[r * 3 + 2], sdz[e] * f);
    }

    // agg[row] += msg (coalesced across j for each edge)
#pragma unroll 4
    for (int e2 = 0; e2 < EH; e2++) {
        int e = hf * EH + e2;
        if (e0 + e < E) {
            long long r = srow[e];
            atomicAdd(&g_agg[r * DD + j], sM[j * STR + e]);
        }
    }
}

#define NODE_SMEM_BYTES ((256 * STR + DD * STR) * 4)   // 55296

__global__ __launch_bounds__(256, 3) void egnn_node_kernel(
    const float* __restrict__ h,
    const float* __restrict__ Wn1, const float* __restrict__ bn1,
    const float* __restrict__ Wn2, const float* __restrict__ bn2,
    float* __restrict__ h_out, int N)
{
    extern __shared__ __align__(16) float smem[];
    float* sA = smem;                 // [256][STR] = [h ; agg] transposed
    float* sT = smem + 256 * STR;     // [128][STR]

    const int t  = threadIdx.x;
    const int j  = t & 127;
    const int hf = t >> 7;
    const long long n0 = (long long)blockIdx.x * TE;

#pragma unroll 4
    for (int e2 = 0; e2 < EH; e2++) {
        int e = hf * EH + e2;
        long long n = n0 + e;
        if (n >= N) n = N - 1;
        sA[j * STR + e]        = h[n * DD + j];
        sA[(DD + j) * STR + e] = g_agg[n * DD + j];
    }
    __syncthreads();

    float v[EH];
    mm_col16<2 * DD>(sA + hf * EH, Wn1, j, v);
    {
        float bj = bn1[j];
        float* dst = sT + j * STR + hf * EH;
#pragma unroll
        for (int g = 0; g < EH / 4; g++) {
            float4 f;
            f.x = silu_f(v[4 * g + 0] + bj);
            f.y = silu_f(v[4 * g + 1] + bj);
            f.z = silu_f(v[4 * g + 2] + bj);
            f.w = silu_f(v[4 * g + 3] + bj);
            *reinterpret_cast<float4*>(dst + 4 * g) = f;
        }
    }
    __syncthreads();

    mm_col16<DD>(sT + hf * EH, Wn2, j, v);
    float bj = bn2[j];
#pragma unroll
    for (int e2 = 0; e2 < EH; e2++) {
        int e = hf * EH + e2;
        long long n = n0 + e;
        if (n < N) h_out[n * DD + j] = h[n * DD + j] + v[e2] + bj;
    }
}

__global__ void egnn_init_kernel(const float* __restrict__ pos,
                                 float* __restrict__ pos_out,
                                 long long nAgg, long long nPos)
{
    long long i = (long long)blockIdx.x * blockDim.x + threadIdx.x;
    if (i < nAgg) g_agg[i] = 0.0f;
    if (i < nPos) pos_out[i] = pos[i];
}

extern "C" void kernel_launch(void* const* d_in, const int* in_sizes, int n_in,
                              void* d_out, int out_size)
{
    const float* h   = (const float*)d_in[0];
    const float* pos = (const float*)d_in[1];
    const int*   ei  = (const int*)d_in[2];   // dtype probed on device (int32 vs int64)
    const float* We1 = (const float*)d_in[3];
    const float* be1 = (const float*)d_in[4];
    const float* We2 = (const float*)d_in[5];
    const float* be2 = (const float*)d_in[6];
    const float* Wn1 = (const float*)d_in[7];
    const float* bn1 = (const float*)d_in[8];
    const float* Wn2 = (const float*)d_in[9];
    const float* bn2 = (const float*)d_in[10];
    const float* Wc1 = (const float*)d_in[11];
    const float* bc1 = (const float*)d_in[12];
    const float* Wc2 = (const float*)d_in[13];

    const int N = in_sizes[0] / DD;
    const long long E = (long long)in_sizes[2] / 2;

    float* h_out   = (float*)d_out;
    float* pos_out = h_out + (long long)N * DD;

    cudaFuncSetAttribute(egnn_edge_kernel, cudaFuncAttributeMaxDynamicSharedMemorySize, EDGE_SMEM_BYTES);
    cudaFuncSetAttribute(egnn_node_kernel, cudaFuncAttributeMaxDynamicSharedMemorySize, NODE_SMEM_BYTES);

    egnn_detect_kernel<<<1, 1>>>(ei);

    long long nAgg = (long long)N * DD;
    long long nPos = (long long)N * 3;
    int ib = (int)((nAgg + 255) / 256);
    egnn_init_kernel<<<ib, 256>>>(pos, pos_out, nAgg, nPos);

    int eb = (int)((E + TE - 1) / TE);
    egnn_edge_kernel<<<eb, 256, EDGE_SMEM_BYTES>>>(
        h, pos, ei, E, We1, be1, We2, be2, Wc1, bc1, Wc2, pos_out);

    int nb = (N + TE - 1) / TE;
    egnn_node_kernel<<<nb, 256, NODE_SMEM_BYTES>>>(
        h, Wn1, bn1, Wn2, bn2, h_out, N);
}

// round 4
// speedup vs baseline: 1.3771x; 1.2565x over previous
#include <cuda_runtime.h>

#define DD 128
#define TE 32      // edges (or nodes) per block
#define STR 36     // row stride in floats: multiple of 4 -> 16B-aligned rows

__device__ float g_agg[50000 * 128];
__device__ int g_is64;

__device__ __forceinline__ unsigned long long pack2f(float lo, float hi) {
    unsigned long long r;
    asm("mov.b64 %0, {%1,%2};" : "=l"(r) : "f"(lo), "f"(hi));
    return r;
}
__device__ __forceinline__ void unpack2f(unsigned long long v, float& lo, float& hi) {
    asm("mov.b64 {%0,%1}, %2;" : "=f"(lo), "=f"(hi) : "l"(v));
}
__device__ __forceinline__ unsigned long long fma2(unsigned long long a, unsigned long long b, unsigned long long c) {
    unsigned long long d;
    asm("fma.rn.f32x2 %0, %1, %2, %3;" : "=l"(d) : "l"(a), "l"(b), "l"(c));
    return d;
}
__device__ __forceinline__ float silu_f(float x) {
    return __fdividef(x, 1.0f + __expf(-x));
}

// Each thread computes 2 adjacent output columns (c0=2jp, c0+1) for 8 edges.
// sIn pre-offset to this thread's 8-edge group (16B aligned).
// Wp = W + 2*jp (row stride DD). out0/out1: 8 floats each.
template<int K>
__device__ __forceinline__ void mm_col2x8(const float* sIn, const float* __restrict__ Wp,
                                          float out0[8], float out1[8]) {
    unsigned long long acc0[4], acc1[4];
#pragma unroll
    for (int p = 0; p < 4; p++) { acc0[p] = 0ull; acc1[p] = 0ull; }

    constexpr int PF = 4;
    float2 w[PF];
#pragma unroll
    for (int i = 0; i < PF; i++)
        w[i] = *reinterpret_cast<const float2*>(Wp + i * DD);

    constexpr int KMAIN = (K / PF) * PF;
#pragma unroll 1
    for (int kb = 0; kb < KMAIN; kb += PF) {
        float2 wn[PF];
#pragma unroll
        for (int i = 0; i < PF; i++) {
            int kk = kb + PF + i;
            wn[i] = (kk < K) ? *reinterpret_cast<const float2*>(Wp + kk * DD)
                             : make_float2(0.f, 0.f);
        }
#pragma unroll
        for (int i = 0; i < PF; i++) {
            unsigned long long ww0 = pack2f(w[i].x, w[i].x);
            unsigned long long ww1 = pack2f(w[i].y, w[i].y);
            const ulonglong2* a2 = reinterpret_cast<const ulonglong2*>(sIn + (kb + i) * STR);
            ulonglong2 p0 = a2[0];
            ulonglong2 p1 = a2[1];
            acc0[0] = fma2(p0.x, ww0, acc0[0]);
            acc1[0] = fma2(p0.x, ww1, acc1[0]);
            acc0[1] = fma2(p0.y, ww0, acc0[1]);
            acc1[1] = fma2(p0.y, ww1, acc1[1]);
            acc0[2] = fma2(p1.x, ww0, acc0[2]);
            acc1[2] = fma2(p1.x, ww1, acc1[2]);
            acc0[3] = fma2(p1.y, ww0, acc0[3]);
            acc1[3] = fma2(p1.y, ww1, acc1[3]);
        }
#pragma unroll
        for (int i = 0; i < PF; i++) w[i] = wn[i];
    }
#pragma unroll
    for (int k = KMAIN; k < K; k++) {   // tail (K=257 -> one k)
        unsigned long long ww0 = pack2f(w[k - KMAIN].x, w[k - KMAIN].x);
        unsigned long long ww1 = pack2f(w[k - KMAIN].y, w[k - KMAIN].y);
        const ulonglong2* a2 = reinterpret_cast<const ulonglong2*>(sIn + k * STR);
        ulonglong2 p0 = a2[0];
        ulonglong2 p1 = a2[1];
        acc0[0] = fma2(p0.x, ww0, acc0[0]);
        acc1[0] = fma2(p0.x, ww1, acc1[0]);
        acc0[1] = fma2(p0.y, ww0, acc0[1]);
        acc1[1] = fma2(p0.y, ww1, acc1[1]);
        acc0[2] = fma2(p1.x, ww0, acc0[2]);
        acc1[2] = fma2(p1.x, ww1, acc1[2]);
        acc0[3] = fma2(p1.y, ww0, acc0[3]);
        acc1[3] = fma2(p1.y, ww1, acc1[3]);
    }
#pragma unroll
    for (int p = 0; p < 4; p++) {
        unpack2f(acc0[p], out0[2 * p], out0[2 * p + 1]);
        unpack2f(acc1[p], out1[2 * p], out1[2 * p + 1]);
    }
}

// Store 2 columns x 8 edges with SiLU(v + bias) into dst tile.
__device__ __forceinline__ void store_silu2(float* dst0, float v0[8], float b0,
                                            float* dst1, float v1[8], float b1) {
#pragma unroll
    for (int g = 0; g < 2; g++) {
        float4 f0, f1;
        f0.x = silu_f(v0[4 * g + 0] + b0);
        f0.y = silu_f(v0[4 * g + 1] + b0);
        f0.z = silu_f(v0[4 * g + 2] + b0);
        f0.w = silu_f(v0[4 * g + 3] + b0);
        f1.x = silu_f(v1[4 * g + 0] + b1);
        f1.y = silu_f(v1[4 * g + 1] + b1);
        f1.z = silu_f(v1[4 * g + 2] + b1);
        f1.w = silu_f(v1[4 * g + 3] + b1);
        *reinterpret_cast<float4*>(dst0 + 4 * g) = f0;
        *reinterpret_cast<float4*>(dst1 + 4 * g) = f1;
    }
}

// smem float offsets (edge kernel); sM overlays sA, sC overlays sT
#define OFF_SA   0
#define OFF_ST   (257 * STR)          // 9252
#define OFF_WC2  (OFF_ST + DD * STR)  // 13860
#define OFF_DX   (OFF_WC2 + DD)
#define OFF_DY   (OFF_DX + TE)
#define OFF_DZ   (OFF_DY + TE)
#define OFF_ID   (OFF_DZ + TE)
#define OFF_ROW  (OFF_ID + TE)
#define OFF_COL  (OFF_ROW + TE)
#define EDGE_SMEM_BYTES ((OFF_COL + TE) * 4)   // 56720

__global__ void egnn_detect_kernel(const int* __restrict__ ei32) {
    int is64 = 1;
#pragma unroll
    for (int i = 1; i < 64; i += 2)
        if (ei32[i] != 0) is64 = 0;
    g_is64 = is64;
}

__global__ __launch_bounds__(256, 3) void egnn_edge_kernel(
    const float* __restrict__ h, const float* __restrict__ pos,
    const int* __restrict__ ei32, long long E,
    const float* __restrict__ We1, const float* __restrict__ be1,
    const float* __restrict__ We2, const float* __restrict__ be2,
    const float* __restrict__ Wc1, const float* __restrict__ bc1,
    const float* __restrict__ Wc2, float* __restrict__ pos_out)
{
    extern __shared__ __align__(16) float smem[];
    float* sA   = smem + OFF_SA;   // [257][STR]; sM overlays after layer 1
    float* sT   = smem + OFF_ST;   // [128][STR]; sC overlays after layer 2
    float* sM   = sA;
    float* sC   = sT;
    float* sWc2 = smem + OFF_WC2;
    float* sdx  = smem + OFF_DX;
    float* sdy  = smem + OFF_DY;
    float* sdz  = smem + OFF_DZ;
    float* sid  = smem + OFF_ID;
    int*   srow = (int*)(smem + OFF_ROW);
    int*   scol = (int*)(smem + OFF_COL);

    const int t  = threadIdx.x;
    const int j  = t & 127;        // gather/scatter map
    const int hf = t >> 7;
    const int jp = t & 63;         // GEMM map: cols {2jp, 2jp+1}
    const int q  = t >> 6;         // edges [8q, 8q+8)
    const int c0 = 2 * jp;
    const long long e0 = (long long)blockIdx.x * TE;

    if (t < DD) sWc2[t] = Wc2[t];
    if (t < TE) {
        long long e = e0 + t;
        if (e >= E) e = E - 1;
        int r, c;
        if (g_is64) { r = ei32[2 * e]; c = ei32[2 * (E + e)]; }
        else        { r = ei32[e];     c = ei32[E + e]; }
        srow[t] = r;
        scol[t] = c;
        float dx = pos[r * 3 + 0] - pos[c * 3 + 0];
        float dy = pos[r * 3 + 1] - pos[c * 3 + 1];
        float dz = pos[r * 3 + 2] - pos[c * 3 + 2];
        float d = sqrtf(dx * dx + dy * dy + dz * dz);
        d = fmaxf(d, 1e-6f);
        sA[256 * STR + t] = d;
        sdx[t] = dx; sdy[t] = dy; sdz[t] = dz;
        sid[t] = 1.0f / d;
    }
    __syncthreads();

    // gather h[row] -> rows 0..127, h[col] -> rows 128..255 (transposed)
#pragma unroll 4
    for (int e2 = 0; e2 < 16; e2++) {
        int e = hf * 16 + e2;
        long long r = srow[e];
        long long c = scol[e];
        sA[j * STR + e]        = h[r * DD + j];
        sA[(DD + j) * STR + e] = h[c * DD + j];
    }
    __syncthreads();

    float v0[8], v1[8];

    // layer 1: [257] -> [128], SiLU
    mm_col2x8<2 * DD + 1>(sA + q * 8, We1 + c0, v0, v1);
    store_silu2(sT + c0 * STR + q * 8, v0, be1[c0],
                sT + (c0 + 1) * STR + q * 8, v1, be1[c0 + 1]);
    __syncthreads();

    // layer 2: [128] -> msg [128], SiLU (writes overlay sA)
    mm_col2x8<DD>(sT + q * 8, We2 + c0, v0, v1);
    store_silu2(sM + c0 * STR + q * 8, v0, be2[c0],
                sM + (c0 + 1) * STR + q * 8, v1, be2[c0 + 1]);
    __syncthreads();

    // layer 3 (coord MLP hidden): msg -> [128], SiLU (writes overlay sT)
    mm_col2x8<DD>(sM + q * 8, Wc1 + c0, v0, v1);
    store_silu2(sC + c0 * STR + q * 8, v0, bc1[c0],
                sC + (c0 + 1) * STR + q * 8, v1, bc1[c0 + 1]);
    __syncthreads();

    // coord weight + pos scatter
    if (t < TE && e0 + t < E) {
        const int e = t;
        float s = 0.f;
#pragma unroll 16
        for (int jj = 0; jj < DD; jj++) s += sC[jj * STR + e] * sWc2[jj];
        s = fminf(fmaxf(s, -1.0f), 1.0f);
        float f = s * sid[e];
        long long r = srow[e];
        atomicAdd(&pos_out[r * 3 + 0], sdx[e] * f);
        atomicAdd(&pos_out[r * 3 + 1], sdy[e] * f);
        atomicAdd(&pos_out[r * 3 + 2], sdz[e] * f);
    }

    // agg[row] += msg (coalesced across j for each edge)
#pragma unroll 4
    for (int e2 = 0; e2 < 16; e2++) {
        int e = hf * 16 + e2;
        if (e0 + e < E) {
            long long r = srow[e];
            atomicAdd(&g_agg[r * DD + j], sM[j * STR + e]);
        }
    }
}

#define NODE_SMEM_BYTES ((256 * STR + DD * STR) * 4)   // 55296

__global__ __launch_bounds__(256, 3) void egnn_node_kernel(
    const float* __restrict__ h,
    const float* __restrict__ Wn1, const float* __restrict__ bn1,
    const float* __restrict__ Wn2, const float* __restrict__ bn2,
    float* __restrict__ h_out, int N)
{
    extern __shared__ __align__(16) float smem[];
    float* sA = smem;                 // [256][STR] = [h ; agg] transposed
    float* sT = smem + 256 * STR;     // [128][STR]

    const int t  = threadIdx.x;
    const int j  = t & 127;
    const int hf = t >> 7;
    const int jp = t & 63;
    const int q  = t >> 6;
    const int c0 = 2 * jp;
    const long long n0 = (long long)blockIdx.x * TE;

#pragma unroll 4
    for (int e2 = 0; e2 < 16; e2++) {
        int e = hf * 16 + e2;
        long long n = n0 + e;
        if (n >= N) n = N - 1;
        sA[j * STR + e]        = h[n * DD + j];
        sA[(DD + j) * STR + e] = g_agg[n * DD + j];
    }
    __syncthreads();

    float v0[8], v1[8];
    mm_col2x8<2 * DD>(sA + q * 8, Wn1 + c0, v0, v1);
    store_silu2(sT + c0 * STR + q * 8, v0, bn1[c0],
                sT + (c0 + 1) * STR + q * 8, v1, bn1[c0 + 1]);
    __syncthreads();

    mm_col2x8<DD>(sT + q * 8, Wn2 + c0, v0, v1);
    float b0 = bn2[c0];
    float b1 = bn2[c0 + 1];
#pragma unroll
    for (int e2 = 0; e2 < 8; e2++) {
        int e = q * 8 + e2;
        long long n = n0 + e;
        if (n < N) {
            float2 hv = *reinterpret_cast<const float2*>(h + n * DD + c0);
            float2 o;
            o.x = hv.x + v0[e2] + b0;
            o.y = hv.y + v1[e2] + b1;
            *reinterpret_cast<float2*>(h_out + n * DD + c0) = o;
        }
    }
}

__global__ void egnn_init_kernel(const float* __restrict__ pos,
                                 float* __restrict__ pos_out,
                                 long long nAgg, long long nPos)
{
    long long i = (long long)blockIdx.x * blockDim.x + threadIdx.x;
    if (i < nAgg) g_agg[i] = 0.0f;
    if (i < nPos) pos_out[i] = pos[i];
}

extern "C" void kernel_launch(void* const* d_in, const int* in_sizes, int n_in,
                              void* d_out, int out_size)
{
    const float* h   = (const float*)d_in[0];
    const float* pos = (const float*)d_in[1];
    const int*   ei  = (const int*)d_in[2];   // dtype probed on device (int32 vs int64)
    const float* We1 = (const float*)d_in[3];
    const float* be1 = (const float*)d_in[4];
    const float* We2 = (const float*)d_in[5];
    const float* be2 = (const float*)d_in[6];
    const float* Wn1 = (const float*)d_in[7];
    const float* bn1 = (const float*)d_in[8];
    const float* Wn2 = (const float*)d_in[9];
    const float* bn2 = (const float*)d_in[10];
    const float* Wc1 = (const float*)d_in[11];
    const float* bc1 = (const float*)d_in[12];
    const float* Wc2 = (const float*)d_in[13];

    const int N = in_sizes[0] / DD;
    const long long E = (long long)in_sizes[2] / 2;

    float* h_out   = (float*)d_out;
    float* pos_out = h_out + (long long)N * DD;

    cudaFuncSetAttribute(egnn_edge_kernel, cudaFuncAttributeMaxDynamicSharedMemorySize, EDGE_SMEM_BYTES);
    cudaFuncSetAttribute(egnn_node_kernel, cudaFuncAttributeMaxDynamicSharedMemorySize, NODE_SMEM_BYTES);

    egnn_detect_kernel<<<1, 1>>>(ei);

    long long nAgg = (long long)N * DD;
    long long nPos = (long long)N * 3;
    int ib = (int)((nAgg + 255) / 256);
    egnn_init_kernel<<<ib, 256>>>(pos, pos_out, nAgg, nPos);

    int eb = (int)((E + TE - 1) / TE);
    egnn_edge_kernel<<<eb, 256, EDGE_SMEM_BYTES>>>(
        h, pos, ei, E, We1, be1, We2, be2, Wc1, bc1, Wc2, pos_out);

    int nb = (N + TE - 1) / TE;
    egnn_node_kernel<<<nb, 256, NODE_SMEM_BYTES>>>(
        h, Wn1, bn1, Wn2, bn2, h_out, N);
}

// round 6
// speedup vs baseline: 1.8374x; 1.3342x over previous
#include <cuda_runtime.h>
#include <cstdint>

#define DD 128
#define TE 32
#define STR 36
#define EPB 256          // edges per block (edge mma kernel)

__device__ float g_agg[50000 * 128];
__device__ int g_is64;
__device__ float g_wimg[8 * 8192];   // 8 fragment-layout weight chunk images (We1 x4, We2 x2, Wc1 x2)

// ---------------- generic helpers ----------------
__device__ __forceinline__ uint32_t smem_u32(const void* p) {
    uint32_t a;
    asm("{ .reg .u64 t; cvta.to.shared.u64 t, %1; cvt.u32.u64 %0, t; }" : "=r"(a) : "l"(p));
    return a;
}
__device__ __forceinline__ float silu_f(float x) { return __fdividef(x, 1.0f + __expf(-x)); }
__device__ __forceinline__ float tf32r(float x) {
    uint32_t o;
    asm("cvt.rna.tf32.f32 %0, %1;" : "=r"(o) : "f"(x));
    return __uint_as_float(o);
}
__device__ __forceinline__ unsigned long long pack2f(float lo, float hi) {
    unsigned long long r;
    asm("mov.b64 %0, {%1,%2};" : "=l"(r) : "f"(lo), "f"(hi));
    return r;
}
__device__ __forceinline__ void unpack2f(unsigned long long v, float& lo, float& hi) {
    asm("mov.b64 {%0,%1}, %2;" : "=f"(lo), "=f"(hi) : "l"(v));
}
__device__ __forceinline__ unsigned long long fma2(unsigned long long a, unsigned long long b, unsigned long long c) {
    unsigned long long d;
    asm("fma.rn.f32x2 %0, %1, %2, %3;" : "=l"(d) : "l"(a), "l"(b), "l"(c));
    return d;
}
__device__ __forceinline__ uint4 lds128(uint32_t a) {
    uint4 v;
    asm volatile("ld.shared.v4.b32 {%0,%1,%2,%3}, [%4];"
                 : "=r"(v.x), "=r"(v.y), "=r"(v.z), "=r"(v.w) : "r"(a));
    return v;
}
__device__ __forceinline__ void mma8(float* c, uint4 a, uint32_t b0, uint32_t b1) {
    asm volatile(
        "mma.sync.aligned.m16n8k8.row.col.f32.tf32.tf32.f32 "
        "{%0,%1,%2,%3}, {%4,%5,%6,%7}, {%8,%9}, {%0,%1,%2,%3};"
        : "+f"(c[0]), "+f"(c[1]), "+f"(c[2]), "+f"(c[3])
        : "r"(a.x), "r"(a.y), "r"(a.z), "r"(a.w), "r"(b0), "r"(b1));
}

// ---------------- smem map (floats / bytes) ----------------
// XB: fragment-layout X region. Full-layout (kstot=16): 256 edges x 128 k = 131072 B.
//     Layer1 uses first half (kstot=8, 64-k chunk buffer).
// WB: one 64k x 128n weight chunk image = 32768 B.
#define XB_B    0
#define WB_B    131072
#define SROW_B  163840
#define SCOL_B  164864
#define SDX_B   165888
#define SDY_B   166912
#define SDZ_B   167936
#define SID_B   168960
#define SDIST_B 169984
#define W257_B  171008
#define SWC2_B  171520
#define SBE1_B  172032
#define SBE2_B  172544
#define SBC1_B  173056
#define EDGE_SMEM_BYTES 173568

// ---------------- small kernels ----------------
__global__ void egnn_detect_kernel(const int* __restrict__ ei32) {
    int is64 = 1;
#pragma unroll
    for (int i = 1; i < 64; i += 2)
        if (ei32[i] != 0) is64 = 0;
    g_is64 = is64;
}

__global__ void egnn_init_kernel(const float* __restrict__ pos,
                                 float* __restrict__ pos_out,
                                 long long nAgg, long long nPos) {
    long long i = (long long)blockIdx.x * blockDim.x + threadIdx.x;
    if (i < nAgg) g_agg[i] = 0.0f;
    if (i < nPos) pos_out[i] = pos[i];
}

// Build fragment-layout tf32 weight images.
// Image float index i: frag = i>>7, lane = (i>>2)&31, reg = i&3.
// frag -> nt = frag>>2, kp = frag&3. n = nt*8 + (lane>>2).
// k_local = kp*16 + (reg>>1)*8 + (reg&1)*4 + (lane&3).
__global__ void egnn_prep_kernel(const float* __restrict__ We1,
                                 const float* __restrict__ We2,
                                 const float* __restrict__ Wc1) {
    int i = blockIdx.x * 256 + threadIdx.x;
    if (i >= 8 * 8192) return;
    int ci = i >> 13;
    int r = i & 8191;
    int frag = r >> 7;
    int lane = (r >> 2) & 31;
    int reg = r & 3;
    int nt = frag >> 2, kp = frag & 3;
    int n = nt * 8 + (lane >> 2);
    int kl = kp * 16 + (reg >> 1) * 8 + (reg & 1) * 4 + (lane & 3);
    const float* W; int kg;
    if (ci < 4)      { W = We1; kg = ci * 64 + kl; }
    else if (ci < 6) { W = We2; kg = (ci - 4) * 64 + kl; }
    else             { W = Wc1; kg = (ci - 6) * 64 + kl; }
    g_wimg[i] = tf32r(W[kg * DD + n]);
}

// ---------------- edge kernel core ----------------
__device__ __forceinline__ void mma_chunk(float (&C)[2][16][4], uint32_t xb_u, uint32_t wb_u,
                                          int mtg0, int ks0, int kstot, int lane) {
#pragma unroll
    for (int kp = 0; kp < 4; kp++) {
        int ks = ks0 + kp * 2;
        uint4 a00 = lds128(xb_u + (uint32_t)((((mtg0 + 0) * kstot + ks) << 9) + lane * 16));
        uint4 a01 = lds128(xb_u + (uint32_t)((((mtg0 + 0) * kstot + ks + 1) << 9) + lane * 16));
        uint4 a10 = lds128(xb_u + (uint32_t)((((mtg0 + 1) * kstot + ks) << 9) + lane * 16));
        uint4 a11 = lds128(xb_u + (uint32_t)((((mtg0 + 1) * kstot + ks + 1) << 9) + lane * 16));
#pragma unroll
        for (int nt = 0; nt < 16; nt++) {
            uint4 b = lds128(wb_u + (uint32_t)(((nt * 4 + kp) << 9) + lane * 16));
            mma8(C[0][nt], a00, b.x, b.y);
            mma8(C[0][nt], a01, b.z, b.w);
            mma8(C[1][nt], a10, b.x, b.y);
            mma8(C[1][nt], a11, b.z, b.w);
        }
    }
}

__global__ __launch_bounds__(256, 1) void egnn_edge_mma(
    const float* __restrict__ h, const float* __restrict__ pos,
    const int* __restrict__ ei32, long long E,
    const float* __restrict__ We1, const float* __restrict__ be1,
    const float* __restrict__ be2, const float* __restrict__ bc1,
    const float* __restrict__ Wc2, float* __restrict__ pos_out)
{
    extern __shared__ __align__(16) float smem[];
    char* sb = (char*)smem;
    const uint32_t sbase = smem_u32(smem);
    float* xbf   = (float*)(sb + XB_B);
    float* wbf   = (float*)(sb + WB_B);
    int*   srow  = (int*)(sb + SROW_B);
    int*   scol  = (int*)(sb + SCOL_B);
    float* sdx   = (float*)(sb + SDX_B);
    float* sdy   = (float*)(sb + SDY_B);
    float* sdz   = (float*)(sb + SDZ_B);
    float* sid   = (float*)(sb + SID_B);
    float* sdist = (float*)(sb + SDIST_B);
    float* w257s = (float*)(sb + W257_B);
    float* swc2  = (float*)(sb + SWC2_B);
    float* sbe1  = (float*)(sb + SBE1_B);
    float* sbe2  = (float*)(sb + SBE2_B);
    float* sbc1  = (float*)(sb + SBC1_B);

    const int t = threadIdx.x;
    const int w = t >> 5;
    const int lane = t & 31;
    const int g = lane >> 2;
    const int tig = lane & 3;
    const long long e0 = (long long)blockIdx.x * EPB;

    // ---- setup: edge meta + small tables ----
    {
        long long e = e0 + t;
        if (e >= E) e = E - 1;
        int r, c;
        if (g_is64) { r = ei32[2 * e]; c = ei32[2 * (E + e)]; }
        else        { r = ei32[e];     c = ei32[E + e]; }
        srow[t] = r; scol[t] = c;
        float dx = pos[r * 3 + 0] - pos[c * 3 + 0];
        float dy = pos[r * 3 + 1] - pos[c * 3 + 1];
        float dz = pos[r * 3 + 2] - pos[c * 3 + 2];
        float d = sqrtf(dx * dx + dy * dy + dz * dz);
        d = fmaxf(d, 1e-6f);
        sdx[t] = dx; sdy[t] = dy; sdz[t] = dz;
        sid[t] = 1.0f / d; sdist[t] = d;
        if (t < DD) {
            w257s[t] = We1[256 * DD + t];   // dist row, kept fp32
            swc2[t]  = Wc2[t];
            sbe1[t]  = be1[t];
            sbe2[t]  = be2[t];
            sbc1[t]  = bc1[t];
        }
    }
    __syncthreads();

    float C[2][16][4];
    const uint32_t xb_u = sbase + XB_B;
    const uint32_t wb_u = sbase + WB_B;
    const int mtg0 = 2 * w;

    // ================= layer 1: K=256 in 4 chunks (+ dist rank-1) =================
#pragma unroll
    for (int mt = 0; mt < 2; mt++)
#pragma unroll
        for (int nt = 0; nt < 16; nt++)
#pragma unroll
            for (int q = 0; q < 4; q++) C[mt][nt][q] = 0.0f;

    for (int c = 0; c < 4; c++) {
        // stage weight chunk (linear copy, layout pre-encoded)
        {
            const float4* src = (const float4*)(g_wimg + c * 8192);
            float4* dst = (float4*)wbf;
#pragma unroll
            for (int i = 0; i < 8; i++) dst[i * 256 + t] = src[i * 256 + t];
        }
        // gather X chunk (conflict-free fragment writes)
        {
#pragma unroll 4
            for (int round = 0; round < 64; round++) {
                int egrp = round >> 3, kblk = round & 7;
                int mtl = egrp >> 2;
                int b2 = (egrp & 3) * 2;
                int rsel = lane >> 3;
                int r = b2 + (rsel & 1) + 8 * (rsel >> 1);
                int k = kblk * 8 + (lane & 7);
                int ew = w * 32 + mtl * 16 + r;
                int node = (c < 2) ? srow[ew] : scol[ew];
                int feat = (c & 1) * 64 + k;
                float v = tf32r(h[(long long)node * DD + feat]);
                int frag = (ew >> 4) * 8 + (k >> 3);
                int ls = (r & 7) * 4 + (k & 3);
                int rg = (r >> 3) + 2 * ((k & 7) >> 2);
                xbf[frag * 128 + ls * 4 + rg] = v;
            }
        }
        __syncthreads();
        mma_chunk(C, xb_u, wb_u, mtg0, 0, 8, lane);
        __syncthreads();
    }

    // epilogue 1: rank-1 dist + bias + silu -> X2 (full layout, kstot=16)
#pragma unroll
    for (int mt = 0; mt < 2; mt++) {
#pragma unroll
        for (int nt = 0; nt < 16; nt++) {
#pragma unroll
            for (int q = 0; q < 4; q++) {
                int n = nt * 8 + 2 * tig + (q & 1);
                int r = g + 8 * (q >> 1);
                int ew = w * 32 + mt * 16 + r;
                float v = C[mt][nt][q] + sdist[ew] * w257s[n] + sbe1[n];
                v = tf32r(silu_f(v));
                int frag = (ew >> 4) * 16 + nt;
                int ls = (r & 7) * 4 + (n & 3);
                int rg = (r >> 3) + 2 * ((n & 7) >> 2);
                xbf[frag * 128 + ls * 4 + rg] = v;
            }
        }
    }

    // ================= layer 2: K=128 in 2 chunks =================
#pragma unroll
    for (int mt = 0; mt < 2; mt++)
#pragma unroll
        for (int nt = 0; nt < 16; nt++)
#pragma unroll
            for (int q = 0; q < 4; q++) C[mt][nt][q] = 0.0f;

    for (int c = 0; c < 2; c++) {
        {
            const float4* src = (const float4*)(g_wimg + (4 + c) * 8192);
            float4* dst = (float4*)wbf;
#pragma unroll
            for (int i = 0; i < 8; i++) dst[i * 256 + t] = src[i * 256 + t];
        }
        __syncthreads();
        mma_chunk(C, xb_u, wb_u, mtg0, 8 * c, 16, lane);
        __syncthreads();
    }

    // epilogue 2: msg = silu(C + be2) -> X3 (overwrite X2)
#pragma unroll
    for (int mt = 0; mt < 2; mt++) {
#pragma unroll
        for (int nt = 0; nt < 16; nt++) {
#pragma unroll
            for (int q = 0; q < 4; q++) {
                int n = nt * 8 + 2 * tig + (q & 1);
                int r = g + 8 * (q >> 1);
                int ew = w * 32 + mt * 16 + r;
                float v = tf32r(silu_f(C[mt][nt][q] + sbe2[n]));
                int frag = (ew >> 4) * 16 + nt;
                int ls = (r & 7) * 4 + (n & 3);
                int rg = (r >> 3) + 2 * ((n & 7) >> 2);
                xbf[frag * 128 + ls * 4 + rg] = v;
            }
        }
    }

    // ================= layer 3: K=128 in 2 chunks =================
#pragma unroll
    for (int mt = 0; mt < 2; mt++)
#pragma unroll
        for (int nt = 0; nt < 16; nt++)
#pragma unroll
            for (int q = 0; q < 4; q++) C[mt][nt][q] = 0.0f;

    for (int c = 0; c < 2; c++) {
        {
            const float4* src = (const float4*)(g_wimg + (6 + c) * 8192);
            float4* dst = (float4*)wbf;
#pragma unroll
            for (int i = 0; i < 8; i++) dst[i * 256 + t] = src[i * 256 + t];
        }
        __syncthreads();
        mma_chunk(C, xb_u, wb_u, mtg0, 8 * c, 16, lane);
        __syncthreads();
    }

    // agg scatter from X3 (smem, coalesced REDG across j)
    {
        int j = t & 127;
        int half = t >> 7;
        int ls_base = j & 3;
        int rg_kpart = 2 * ((j & 7) >> 2);
        int ntj = j >> 3;
#pragma unroll 4
        for (int el = 0; el < 128; el++) {
            int ew = half * 128 + el;
            if (e0 + ew < E) {
                int r = ew & 15;
                int frag = (ew >> 4) * 16 + ntj;
                int ls = (r & 7) * 4 + ls_base;
                int rg = (r >> 3) + rg_kpart;
                float m = xbf[frag * 128 + ls * 4 + rg];
                atomicAdd(&g_agg[(long long)srow[ew] * DD + j], m);
            }
        }
    }

    // coord epilogue: s[e] = clip(sum_n silu(C + bc1[n]) * wc2[n]); pos scatter
    {
        float sp[2][2] = {{0.f, 0.f}, {0.f, 0.f}};
#pragma unroll
        for (int mt = 0; mt < 2; mt++) {
#pragma unroll
            for (int nt = 0; nt < 16; nt++) {
#pragma unroll
                for (int q = 0; q < 4; q++) {
                    int n = nt * 8 + 2 * tig + (q & 1);
                    float v = silu_f(C[mt][nt][q] + sbc1[n]) * swc2[n];
                    sp[mt][q >> 1] += v;
                }
            }
        }
#pragma unroll
        for (int mt = 0; mt < 2; mt++) {
#pragma unroll
            for (int hb = 0; hb < 2; hb++) {
                float s = sp[mt][hb];
                s += __shfl_xor_sync(0xFFFFFFFFu, s, 1);
                s += __shfl_xor_sync(0xFFFFFFFFu, s, 2);
                sp[mt][hb] = s;
            }
        }
        if (tig == 0) {
#pragma unroll
            for (int mt = 0; mt < 2; mt++) {
#pragma unroll
                for (int hb = 0; hb < 2; hb++) {
                    int ew = w * 32 + mt * 16 + g + 8 * hb;
                    if (e0 + ew < E) {
                        float s = fminf(fmaxf(sp[mt][hb], -1.0f), 1.0f);
                        float fac = s * sid[ew];
                        long long rr = srow[ew];
                        atomicAdd(&pos_out[rr * 3 + 0], sdx[ew] * fac);
                        atomicAdd(&pos_out[rr * 3 + 1], sdy[ew] * fac);
                        atomicAdd(&pos_out[rr * 3 + 2], sdz[ew] * fac);
                    }
                }
            }
        }
    }
}

// ---------------- node kernel (SIMT, from R4) ----------------
template<int K>
__device__ __forceinline__ void mm_col2x8(const float* sIn, const float* __restrict__ Wp,
                                          float out0[8], float out1[8]) {
    unsigned long long acc0[4], acc1[4];
#pragma unroll
    for (int p = 0; p < 4; p++) { acc0[p] = 0ull; acc1[p] = 0ull; }
    constexpr int PF = 4;
    float2 w[PF];
#pragma unroll
    for (int i = 0; i < PF; i++)
        w[i] = *reinterpret_cast<const float2*>(Wp + i * DD);
    constexpr int KMAIN = (K / PF) * PF;
#pragma unroll 1
    for (int kb = 0; kb < KMAIN; kb += PF) {
        float2 wn[PF];
#pragma unroll
        for (int i = 0; i < PF; i++) {
            int kk = kb + PF + i;
            wn[i] = (kk < K) ? *reinterpret_cast<const float2*>(Wp + kk * DD)
                             : make_float2(0.f, 0.f);
        }
#pragma unroll
        for (int i = 0; i < PF; i++) {
            unsigned long long ww0 = pack2f(w[i].x, w[i].x);
            unsigned long long ww1 = pack2f(w[i].y, w[i].y);
            const ulonglong2* a2 = reinterpret_cast<const ulonglong2*>(sIn + (kb + i) * STR);
            ulonglong2 p0 = a2[0];
            ulonglong2 p1 = a2[1];
            acc0[0] = fma2(p0.x, ww0, acc0[0]);
            acc1[0] = fma2(p0.x, ww1, acc1[0]);
            acc0[1] = fma2(p0.y, ww0, acc0[1]);
            acc1[1] = fma2(p0.y, ww1, acc1[1]);
            acc0[2] = fma2(p1.x, ww0, acc0[2]);
            acc1[2] = fma2(p1.x, ww1, acc1[2]);
            acc0[3] = fma2(p1.y, ww0, acc0[3]);
            acc1[3] = fma2(p1.y, ww1, acc1[3]);
        }
#pragma unroll
        for (int i = 0; i < PF; i++) w[i] = wn[i];
    }
#pragma unroll
    for (int p = 0; p < 4; p++) {
        unpack2f(acc0[p], out0[2 * p], out0[2 * p + 1]);
        unpack2f(acc1[p], out1[2 * p], out1[2 * p + 1]);
    }
}

__device__ __forceinline__ void store_silu2(float* dst0, float v0[8], float b0,
                                            float* dst1, float v1[8], float b1) {
#pragma unroll
    for (int gg = 0; gg < 2; gg++) {
        float4 f0, f1;
        f0.x = silu_f(v0[4 * gg + 0] + b0);
        f0.y = silu_f(v0[4 * gg + 1] + b0);
        f0.z = silu_f(v0[4 * gg + 2] + b0);
        f0.w = silu_f(v0[4 * gg + 3] + b0);
        f1.x = silu_f(v1[4 * gg + 0] + b1);
        f1.y = silu_f(v1[4 * gg + 1] + b1);
        f1.z = silu_f(v1[4 * gg + 2] + b1);
        f1.w = silu_f(v1[4 * gg + 3] + b1);
        *reinterpret_cast<float4*>(dst0 + 4 * gg) = f0;
        *reinterpret_cast<float4*>(dst1 + 4 * gg) = f1;
    }
}

#define NODE_SMEM_BYTES ((256 * STR + DD * STR) * 4)

__global__ __launch_bounds__(256, 3) void egnn_node_kernel(
    const float* __restrict__ h,
    const float* __restrict__ Wn1, const float* __restrict__ bn1,
    const float* __restrict__ Wn2, const float* __restrict__ bn2,
    float* __restrict__ h_out, int N)
{
    extern __shared__ float smem[];
    float* sA = smem;
    float* sT = smem + 256 * STR;

    const int t  = threadIdx.x;
    const int j  = t & 127;
    const int hf = t >> 7;
    const int jp = t & 63;
    const int q  = t >> 6;
    const int c0 = 2 * jp;
    const long long n0 = (long long)blockIdx.x * TE;

#pragma unroll 4
    for (int e2 = 0; e2 < 16; e2++) {
        int e = hf * 16 + e2;
        long long n = n0 + e;
        if (n >= N) n = N - 1;
        sA[j * STR + e]        = h[n * DD + j];
        sA[(DD + j) * STR + e] = g_agg[n * DD + j];
    }
    __syncthreads();

    float v0[8], v1[8];
    mm_col2x8<2 * DD>(sA + q * 8, Wn1 + c0, v0, v1);
    store_silu2(sT + c0 * STR + q * 8, v0, bn1[c0],
                sT + (c0 + 1) * STR + q * 8, v1, bn1[c0 + 1]);
    __syncthreads();

    mm_col2x8<DD>(sT + q * 8, Wn2 + c0, v0, v1);
    float b0 = bn2[c0];
    float b1 = bn2[c0 + 1];
#pragma unroll
    for (int e2 = 0; e2 < 8; e2++) {
        int e = q * 8 + e2;
        long long n = n0 + e;
        if (n < N) {
            float2 hv = *reinterpret_cast<const float2*>(h + n * DD + c0);
            float2 o;
            o.x = hv.x + v0[e2] + b0;
            o.y = hv.y + v1[e2] + b1;
            *reinterpret_cast<float2*>(h_out + n * DD + c0) = o;
        }
    }
}

// ---------------- launcher ----------------
extern "C" void kernel_launch(void* const* d_in, const int* in_sizes, int n_in,
                              void* d_out, int out_size)
{
    const float* h   = (const float*)d_in[0];
    const float* pos = (const float*)d_in[1];
    const int*   ei  = (const int*)d_in[2];
    const float* We1 = (const float*)d_in[3];
    const float* be1 = (const float*)d_in[4];
    const float* We2 = (const float*)d_in[5];
    const float* be2 = (const float*)d_in[6];
    const float* Wn1 = (const float*)d_in[7];
    const float* bn1 = (const float*)d_in[8];
    const float* Wn2 = (const float*)d_in[9];
    const float* bn2 = (const float*)d_in[10];
    const float* Wc1 = (const float*)d_in[11];
    const float* bc1 = (const float*)d_in[12];
    const float* Wc2 = (const float*)d_in[13];

    const int N = in_sizes[0] / DD;
    const long long E = (long long)in_sizes[2] / 2;

    float* h_out   = (float*)d_out;
    float* pos_out = h_out + (long long)N * DD;

    cudaFuncSetAttribute(egnn_edge_mma, cudaFuncAttributeMaxDynamicSharedMemorySize, EDGE_SMEM_BYTES);
    cudaFuncSetAttribute(egnn_node_kernel, cudaFuncAttributeMaxDynamicSharedMemorySize, NODE_SMEM_BYTES);

    egnn_detect_kernel<<<1, 1>>>(ei);
    egnn_prep_kernel<<<(8 * 8192 + 255) / 256, 256>>>(We1, We2, Wc1);

    long long nAgg = (long long)N * DD;
    long long nPos = (long long)N * 3;
    int ib = (int)((nAgg + 255) / 256);
    egnn_init_kernel<<<ib, 256>>>(pos, pos_out, nAgg, nPos);

    int eb = (int)((E + EPB - 1) / EPB);
    egnn_edge_mma<<<eb, 256, EDGE_SMEM_BYTES>>>(
        h, pos, ei, E, We1, be1, be2, bc1, Wc2, pos_out);

    int nb = (N + TE - 1) / TE;
    egnn_node_kernel<<<nb, 256, NODE_SMEM_BYTES>>>(
        h, Wn1, bn1, Wn2, bn2, h_out, N);
}

// round 7
// speedup vs baseline: 3.5562x; 1.9355x over previous
#include <cuda_runtime.h>
#include <cstdint>

#define DD 128
#define TE 32
#define STR 36
#define EPB 256          // edges per block (edge mma kernel)

__device__ float g_agg[50000 * 128];
__device__ int g_is64;
__device__ float g_wimg[8 * 8192];   // fragment-layout tf32 weight chunks (We1 x4, We2 x2, Wc1 x2)

// ---------------- generic helpers ----------------
__device__ __forceinline__ uint32_t smem_u32(const void* p) {
    uint32_t a;
    asm("{ .reg .u64 t; cvta.to.shared.u64 t, %1; cvt.u32.u64 %0, t; }" : "=r"(a) : "l"(p));
    return a;
}
__device__ __forceinline__ float silu_f(float x) { return __fdividef(x, 1.0f + __expf(-x)); }
__device__ __forceinline__ float tf32r(float x) {
    uint32_t o;
    asm("cvt.rna.tf32.f32 %0, %1;" : "=r"(o) : "f"(x));
    return __uint_as_float(o);
}
__device__ __forceinline__ unsigned long long pack2f(float lo, float hi) {
    unsigned long long r;
    asm("mov.b64 %0, {%1,%2};" : "=l"(r) : "f"(lo), "f"(hi));
    return r;
}
__device__ __forceinline__ void unpack2f(unsigned long long v, float& lo, float& hi) {
    asm("mov.b64 {%0,%1}, %2;" : "=f"(lo), "=f"(hi) : "l"(v));
}
__device__ __forceinline__ unsigned long long fma2(unsigned long long a, unsigned long long b, unsigned long long c) {
    unsigned long long d;
    asm("fma.rn.f32x2 %0, %1, %2, %3;" : "=l"(d) : "l"(a), "l"(b), "l"(c));
    return d;
}
__device__ __forceinline__ uint4 lds128(uint32_t a) {
    uint4 v;
    asm volatile("ld.shared.v4.b32 {%0,%1,%2,%3}, [%4];"
                 : "=r"(v.x), "=r"(v.y), "=r"(v.z), "=r"(v.w) : "r"(a));
    return v;
}
__device__ __forceinline__ void mma8(float* c, uint4 a, uint32_t b0, uint32_t b1) {
    asm volatile(
        "mma.sync.aligned.m16n8k8.row.col.f32.tf32.tf32.f32 "
        "{%0,%1,%2,%3}, {%4,%5,%6,%7}, {%8,%9}, {%0,%1,%2,%3};"
        : "+f"(c[0]), "+f"(c[1]), "+f"(c[2]), "+f"(c[3])
        : "r"(a.x), "r"(a.y), "r"(a.z), "r"(a.w), "r"(b0), "r"(b1));
}

#define CP_ASYNC_4(dst, src) \
    asm volatile("cp.async.ca.shared.global [%0], [%1], 4;" :: "r"(dst), "l"(src) : "memory")
#define CP_ASYNC_16(dst, src) \
    asm volatile("cp.async.cg.shared.global [%0], [%1], 16;" :: "r"(dst), "l"(src) : "memory")
#define CP_COMMIT() asm volatile("cp.async.commit_group;" ::: "memory")
#define CP_WAIT(n)  asm volatile("cp.async.wait_group %0;" :: "n"(n) : "memory")

// ---------------- smem map (bytes) ----------------
// XB: 128KB. Layer1: two 64KB chunk ring buffers. Layers 2/3: full fragment layout (kstot=16).
// WB: two 32KB weight chunk ring buffers.
#define XB_B    0
#define WB_B    131072
#define SROW_B  196608
#define SCOL_B  197632
#define SDX_B   198656
#define SDY_B   199680
#define SDZ_B   200704
#define SID_B   201728
#define SDIST_B 202752
#define W257_B  203776
#define SWC2_B  204288
#define SBE1_B  204800
#define SBE2_B  205312
#define SBC1_B  205824
#define EDGE_SMEM_BYTES 206336

// ---------------- small kernels ----------------
__global__ void egnn_detect_kernel(const int* __restrict__ ei32) {
    int is64 = 1;
#pragma unroll
    for (int i = 1; i < 64; i += 2)
        if (ei32[i] != 0) is64 = 0;
    g_is64 = is64;
}

__global__ void egnn_init_kernel(const float* __restrict__ pos,
                                 float* __restrict__ pos_out,
                                 long long nAgg, long long nPos) {
    long long i = (long long)blockIdx.x * blockDim.x + threadIdx.x;
    if (i < nAgg) g_agg[i] = 0.0f;
    if (i < nPos) pos_out[i] = pos[i];
}

// Build fragment-layout tf32 weight images (same encoding as R6).
__global__ void egnn_prep_kernel(const float* __restrict__ We1,
                                 const float* __restrict__ We2,
                                 const float* __restrict__ Wc1) {
    int i = blockIdx.x * 256 + threadIdx.x;
    if (i >= 8 * 8192) return;
    int ci = i >> 13;
    int r = i & 8191;
    int frag = r >> 7;
    int lane = (r >> 2) & 31;
    int reg = r & 3;
    int nt = frag >> 2, kp = frag & 3;
    int n = nt * 8 + (lane >> 2);
    int kl = kp * 16 + (reg >> 1) * 8 + (reg & 1) * 4 + (lane & 3);
    const float* W; int kg;
    if (ci < 4)      { W = We1; kg = ci * 64 + kl; }
    else if (ci < 6) { W = We2; kg = (ci - 4) * 64 + kl; }
    else             { W = Wc1; kg = (ci - 6) * 64 + kl; }
    g_wimg[i] = tf32r(W[kg * DD + n]);
}

// ---------------- edge kernel pieces ----------------
__device__ __forceinline__ void mma_chunk(float (&C)[2][16][4], uint32_t xbase_u, uint32_t wbase_u,
                                          int mtg0, int ks0, int kstot, int lane) {
#pragma unroll
    for (int kp = 0; kp < 4; kp++) {
        int ks = ks0 + kp * 2;
        uint4 a00 = lds128(xbase_u + (uint32_t)((((mtg0 + 0) * kstot + ks) << 9) + lane * 16));
        uint4 a01 = lds128(xbase_u + (uint32_t)((((mtg0 + 0) * kstot + ks + 1) << 9) + lane * 16));
        uint4 a10 = lds128(xbase_u + (uint32_t)((((mtg0 + 1) * kstot + ks) << 9) + lane * 16));
        uint4 a11 = lds128(xbase_u + (uint32_t)((((mtg0 + 1) * kstot + ks + 1) << 9) + lane * 16));
#pragma unroll
        for (int nt = 0; nt < 16; nt++) {
            uint4 b = lds128(wbase_u + (uint32_t)(((nt * 4 + kp) << 9) + lane * 16));
            mma8(C[0][nt], a00, b.x, b.y);
            mma8(C[0][nt], a01, b.z, b.w);
            mma8(C[1][nt], a10, b.x, b.y);
            mma8(C[1][nt], a11, b.z, b.w);
        }
    }
}

// Stage one 32KB weight chunk (async).
__device__ __forceinline__ void stageW_async(uint32_t wbuf_u, const float* __restrict__ img, int t) {
#pragma unroll
    for (int i = 0; i < 8; i++)
        CP_ASYNC_16(wbuf_u + (uint32_t)((i * 256 + t) * 16), (const char*)(img + (i * 256 + t) * 4));
}

// Async gather of one 64-k X chunk into chunk fragment layout (kstot=8).
__device__ __forceinline__ void gather_chunk_async(uint32_t dstbase_u, int c, int w, int lane,
                                                   const float* __restrict__ h,
                                                   const int* srow, const int* scol) {
    const int rsel = lane >> 3;
    const int radd = (rsel & 1) + 8 * (rsel >> 1);
    const uint32_t dfix = (uint32_t)(((lane & 3)) * 16 + (2 * ((lane & 7) >> 2)) * 4);
#pragma unroll
    for (int egrp = 0; egrp < 8; egrp++) {
        int mtl = egrp >> 2;
        int b2 = (egrp & 3) * 2;
        int r = b2 + radd;
        int ew = w * 32 + mtl * 16 + r;
        int node = (c < 2) ? srow[ew] : scol[ew];
        const char* src = (const char*)(h + (long long)node * DD + (c & 1) * 64 + (lane & 7));
        uint32_t dst = dstbase_u + (uint32_t)((ew >> 4) * 4096 + (r & 7) * 64 + (r >> 3) * 4) + dfix;
#pragma unroll
        for (int kblk = 0; kblk < 8; kblk++) {
            CP_ASYNC_4(dst, src);
            dst += 512;
            src += 32;
        }
    }
}

__global__ __launch_bounds__(256, 1) void egnn_edge_mma(
    const float* __restrict__ h, const float* __restrict__ pos,
    const int* __restrict__ ei32, long long E,
    const float* __restrict__ We1, const float* __restrict__ be1,
    const float* __restrict__ be2, const float* __restrict__ bc1,
    const float* __restrict__ Wc2, float* __restrict__ pos_out)
{
    extern __shared__ __align__(16) float smem[];
    char* sb = (char*)smem;
    const uint32_t sbase = smem_u32(smem);
    float* xbf   = (float*)(sb + XB_B);
    int*   srow  = (int*)(sb + SROW_B);
    int*   scol  = (int*)(sb + SCOL_B);
    float* sdx   = (float*)(sb + SDX_B);
    float* sdy   = (float*)(sb + SDY_B);
    float* sdz   = (float*)(sb + SDZ_B);
    float* sid   = (float*)(sb + SID_B);
    float* sdist = (float*)(sb + SDIST_B);
    float* w257s = (float*)(sb + W257_B);
    float* swc2  = (float*)(sb + SWC2_B);
    float* sbe1  = (float*)(sb + SBE1_B);
    float* sbe2  = (float*)(sb + SBE2_B);
    float* sbc1  = (float*)(sb + SBC1_B);

    const int t = threadIdx.x;
    const int w = t >> 5;
    const int lane = t & 31;
    const int g = lane >> 2;
    const int tig = lane & 3;
    const long long e0 = (long long)blockIdx.x * EPB;

    // ---- setup: edge meta + small tables ----
    {
        long long e = e0 + t;
        if (e >= E) e = E - 1;
        int r, c;
        if (g_is64) { r = ei32[2 * e]; c = ei32[2 * (E + e)]; }
        else        { r = ei32[e];     c = ei32[E + e]; }
        srow[t] = r; scol[t] = c;
        float dx = pos[r * 3 + 0] - pos[c * 3 + 0];
        float dy = pos[r * 3 + 1] - pos[c * 3 + 1];
        float dz = pos[r * 3 + 2] - pos[c * 3 + 2];
        float d = sqrtf(dx * dx + dy * dy + dz * dz);
        d = fmaxf(d, 1e-6f);
        sdx[t] = dx; sdy[t] = dy; sdz[t] = dz;
        sid[t] = 1.0f / d; sdist[t] = d;
        if (t < DD) {
            w257s[t] = We1[256 * DD + t];   // dist row, kept fp32
            swc2[t]  = Wc2[t];
            sbe1[t]  = be1[t];
            sbe2[t]  = be2[t];
            sbc1[t]  = bc1[t];
        }
    }
    __syncthreads();

    float C[2][16][4];
    const uint32_t xb0 = sbase + XB_B;
    const uint32_t wb0 = sbase + WB_B;
    const int mtg0 = 2 * w;

    // ================= layer 1: K=256 in 4 pipelined chunks =================
#pragma unroll
    for (int mt = 0; mt < 2; mt++)
#pragma unroll
        for (int nt = 0; nt < 16; nt++)
#pragma unroll
            for (int q = 0; q < 4; q++) C[mt][nt][q] = 0.0f;

    stageW_async(wb0, g_wimg + 0 * 8192, t);
    gather_chunk_async(xb0, 0, w, lane, h, srow, scol);
    CP_COMMIT();

    for (int c = 0; c < 4; c++) {
        if (c > 0) __syncthreads();          // ring slot (c+1)&1 free from mma(c-1)
        if (c < 3) {
            int b = (c + 1) & 1;
            stageW_async(wb0 + b * 32768, g_wimg + (c + 1) * 8192, t);
            gather_chunk_async(xb0 + b * 65536, c + 1, w, lane, h, srow, scol);
            CP_COMMIT();
            CP_WAIT(1);
        } else {
            CP_WAIT(0);
        }
        __syncthreads();
        int b = c & 1;
        mma_chunk(C, xb0 + b * 65536, wb0 + b * 32768, mtg0, 0, 8, lane);
    }
    __syncthreads();                         // mma(3) done everywhere

    // stage layer-2 W chunk 0 during epilogue
    stageW_async(wb0, g_wimg + 4 * 8192, t);
    CP_COMMIT();

    // epilogue 1: rank-1 dist + bias + silu -> X2 (full layout, kstot=16)
#pragma unroll
    for (int mt = 0; mt < 2; mt++) {
#pragma unroll
        for (int nt = 0; nt < 16; nt++) {
#pragma unroll
            for (int q = 0; q < 4; q++) {
                int n = nt * 8 + 2 * tig + (q & 1);
                int r = g + 8 * (q >> 1);
                int ew = w * 32 + mt * 16 + r;
                float v = C[mt][nt][q] + sdist[ew] * w257s[n] + sbe1[n];
                v = tf32r(silu_f(v));
                int frag = (ew >> 4) * 16 + nt;
                int ls = (r & 7) * 4 + (n & 3);
                int rg = (r >> 3) + 2 * ((n & 7) >> 2);
                xbf[frag * 128 + ls * 4 + rg] = v;
            }
        }
    }
    __syncthreads();                         // X2 visible

    // ================= layer 2: K=128 in 2 pipelined chunks =================
#pragma unroll
    for (int mt = 0; mt < 2; mt++)
#pragma unroll
        for (int nt = 0; nt < 16; nt++)
#pragma unroll
            for (int q = 0; q < 4; q++) C[mt][nt][q] = 0.0f;

    // c = 0
    stageW_async(wb0 + 32768, g_wimg + 5 * 8192, t);
    CP_COMMIT();
    CP_WAIT(1);
    __syncthreads();
    mma_chunk(C, xb0, wb0, mtg0, 0, 16, lane);
    __syncthreads();                         // buf0 free
    // c = 1 (stage layer-3 chunk 0 into buf0 concurrently)
    stageW_async(wb0, g_wimg + 6 * 8192, t);
    CP_COMMIT();
    CP_WAIT(1);
    __syncthreads();
    mma_chunk(C, xb0, wb0 + 32768, mtg0, 8, 16, lane);
    __syncthreads();                         // buf1 free; all mma L2 done

    // stage layer-3 chunk 1 during epilogue
    stageW_async(wb0 + 32768, g_wimg + 7 * 8192, t);
    CP_COMMIT();

    // epilogue 2: msg = silu(C + be2) -> X3 (overwrite X2)
#pragma unroll
    for (int mt = 0; mt < 2; mt++) {
#pragma unroll
        for (int nt = 0; nt < 16; nt++) {
#pragma unroll
            for (int q = 0; q < 4; q++) {
                int n = nt * 8 + 2 * tig + (q & 1);
                int r = g + 8 * (q >> 1);
                int ew = w * 32 + mt * 16 + r;
                float v = tf32r(silu_f(C[mt][nt][q] + sbe2[n]));
                int frag = (ew >> 4) * 16 + nt;
                int ls = (r & 7) * 4 + (n & 3);
                int rg = (r >> 3) + 2 * ((n & 7) >> 2);
                xbf[frag * 128 + ls * 4 + rg] = v;
            }
        }
    }
    __syncthreads();                         // X3 visible

    // ================= layer 3: K=128 in 2 chunks (weights prestaged) =================
#pragma unroll
    for (int mt = 0; mt < 2; mt++)
#pragma unroll
        for (int nt = 0; nt < 16; nt++)
#pragma unroll
            for (int q = 0; q < 4; q++) C[mt][nt][q] = 0.0f;

    CP_WAIT(1);
    __syncthreads();
    mma_chunk(C, xb0, wb0, mtg0, 0, 16, lane);
    CP_WAIT(0);
    __syncthreads();
    mma_chunk(C, xb0, wb0 + 32768, mtg0, 8, 16, lane);

    // agg scatter from X3 (smem, coalesced REDG across j)
    {
        int j = t & 127;
        int half = t >> 7;
        int ls_base = j & 3;
        int rg_kpart = 2 * ((j & 7) >> 2);
        int ntj = j >> 3;
#pragma unroll 4
        for (int el = 0; el < 128; el++) {
            int ew = half * 128 + el;
            if (e0 + ew < E) {
                int r = ew & 15;
                int frag = (ew >> 4) * 16 + ntj;
                int ls = (r & 7) * 4 + ls_base;
                int rg = (r >> 3) + rg_kpart;
                float m = xbf[frag * 128 + ls * 4 + rg];
                atomicAdd(&g_agg[(long long)srow[ew] * DD + j], m);
            }
        }
    }

    // coord epilogue: s[e] = clip(sum_n silu(C + bc1[n]) * wc2[n]); pos scatter
    {
        float sp[2][2] = {{0.f, 0.f}, {0.f, 0.f}};
#pragma unroll
        for (int mt = 0; mt < 2; mt++) {
#pragma unroll
            for (int nt = 0; nt < 16; nt++) {
#pragma unroll
                for (int q = 0; q < 4; q++) {
                    int n = nt * 8 + 2 * tig + (q & 1);
                    float v = silu_f(C[mt][nt][q] + sbc1[n]) * swc2[n];
                    sp[mt][q >> 1] += v;
                }
            }
        }
#pragma unroll
        for (int mt = 0; mt < 2; mt++) {
#pragma unroll
            for (int hb = 0; hb < 2; hb++) {
                float s = sp[mt][hb];
                s += __shfl_xor_sync(0xFFFFFFFFu, s, 1);
                s += __shfl_xor_sync(0xFFFFFFFFu, s, 2);
                sp[mt][hb] = s;
            }
        }
        if (tig == 0) {
#pragma unroll
            for (int mt = 0; mt < 2; mt++) {
#pragma unroll
                for (int hb = 0; hb < 2; hb++) {
                    int ew = w * 32 + mt * 16 + g + 8 * hb;
                    if (e0 + ew < E) {
                        float s = fminf(fmaxf(sp[mt][hb], -1.0f), 1.0f);
                        float fac = s * sid[ew];
                        long long rr = srow[ew];
                        atomicAdd(&pos_out[rr * 3 + 0], sdx[ew] * fac);
                        atomicAdd(&pos_out[rr * 3 + 1], sdy[ew] * fac);
                        atomicAdd(&pos_out[rr * 3 + 2], sdz[ew] * fac);
                    }
                }
            }
        }
    }
}

// ---------------- node kernel (SIMT, from R4) ----------------
template<int K>
__device__ __forceinline__ void mm_col2x8(const float* sIn, const float* __restrict__ Wp,
                                          float out0[8], float out1[8]) {
    unsigned long long acc0[4], acc1[4];
#pragma unroll
    for (int p = 0; p < 4; p++) { acc0[p] = 0ull; acc1[p] = 0ull; }
    constexpr int PF = 4;
    float2 w[PF];
#pragma unroll
    for (int i = 0; i < PF; i++)
        w[i] = *reinterpret_cast<const float2*>(Wp + i * DD);
    constexpr int KMAIN = (K / PF) * PF;
#pragma unroll 1
    for (int kb = 0; kb < KMAIN; kb += PF) {
        float2 wn[PF];
#pragma unroll
        for (int i = 0; i < PF; i++) {
            int kk = kb + PF + i;
            wn[i] = (kk < K) ? *reinterpret_cast<const float2*>(Wp + kk * DD)
                             : make_float2(0.f, 0.f);
        }
#pragma unroll
        for (int i = 0; i < PF; i++) {
            unsigned long long ww0 = pack2f(w[i].x, w[i].x);
            unsigned long long ww1 = pack2f(w[i].y, w[i].y);
            const ulonglong2* a2 = reinterpret_cast<const ulonglong2*>(sIn + (kb + i) * STR);
            ulonglong2 p0 = a2[0];
            ulonglong2 p1 = a2[1];
            acc0[0] = fma2(p0.x, ww0, acc0[0]);
            acc1[0] = fma2(p0.x, ww1, acc1[0]);
            acc0[1] = fma2(p0.y, ww0, acc0[1]);
            acc1[1] = fma2(p0.y, ww1, acc1[1]);
            acc0[2] = fma2(p1.x, ww0, acc0[2]);
            acc1[2] = fma2(p1.x, ww1, acc1[2]);
            acc0[3] = fma2(p1.y, ww0, acc0[3]);
            acc1[3] = fma2(p1.y, ww1, acc1[3]);
        }
#pragma unroll
        for (int i = 0; i < PF; i++) w[i] = wn[i];
    }
#pragma unroll
    for (int p = 0; p < 4; p++) {
        unpack2f(acc0[p], out0[2 * p], out0[2 * p + 1]);
        unpack2f(acc1[p], out1[2 * p], out1[2 * p + 1]);
    }
}

__device__ __forceinline__ void store_silu2(float* dst0, float v0[8], float b0,
                                            float* dst1, float v1[8], float b1) {
#pragma unroll
    for (int gg = 0; gg < 2; gg++) {
        float4 f0, f1;
        f0.x = silu_f(v0[4 * gg + 0] + b0);
        f0.y = silu_f(v0[4 * gg + 1] + b0);
        f0.z = silu_f(v0[4 * gg + 2] + b0);
        f0.w = silu_f(v0[4 * gg + 3] + b0);
        f1.x = silu_f(v1[4 * gg + 0] + b1);
        f1.y = silu_f(v1[4 * gg + 1] + b1);
        f1.z = silu_f(v1[4 * gg + 2] + b1);
        f1.w = silu_f(v1[4 * gg + 3] + b1);
        *reinterpret_cast<float4*>(dst0 + 4 * gg) = f0;
        *reinterpret_cast<float4*>(dst1 + 4 * gg) = f1;
    }
}

#define NODE_SMEM_BYTES ((256 * STR + DD * STR) * 4)

__global__ __launch_bounds__(256, 3) void egnn_node_kernel(
    const float* __restrict__ h,
    const float* __restrict__ Wn1, const float* __restrict__ bn1,
    const float* __restrict__ Wn2, const float* __restrict__ bn2,
    float* __restrict__ h_out, int N)
{
    extern __shared__ float smem[];
    float* sA = smem;
    float* sT = smem + 256 * STR;

    const int t  = threadIdx.x;
    const int j  = t & 127;
    const int hf = t >> 7;
    const int jp = t & 63;
    const int q  = t >> 6;
    const int c0 = 2 * jp;
    const long long n0 = (long long)blockIdx.x * TE;

#pragma unroll 4
    for (int e2 = 0; e2 < 16; e2++) {
        int e = hf * 16 + e2;
        long long n = n0 + e;
        if (n >= N) n = N - 1;
        sA[j * STR + e]        = h[n * DD + j];
        sA[(DD + j) * STR + e] = g_agg[n * DD + j];
    }
    __syncthreads();

    float v0[8], v1[8];
    mm_col2x8<2 * DD>(sA + q * 8, Wn1 + c0, v0, v1);
    store_silu2(sT + c0 * STR + q * 8, v0, bn1[c0],
                sT + (c0 + 1) * STR + q * 8, v1, bn1[c0 + 1]);
    __syncthreads();

    mm_col2x8<DD>(sT + q * 8, Wn2 + c0, v0, v1);
    float b0 = bn2[c0];
    float b1 = bn2[c0 + 1];
#pragma unroll
    for (int e2 = 0; e2 < 8; e2++) {
        int e = q * 8 + e2;
        long long n = n0 + e;
        if (n < N) {
            float2 hv = *reinterpret_cast<const float2*>(h + n * DD + c0);
            float2 o;
            o.x = hv.x + v0[e2] + b0;
            o.y = hv.y + v1[e2] + b1;
            *reinterpret_cast<float2*>(h_out + n * DD + c0) = o;
        }
    }
}

// ---------------- launcher ----------------
extern "C" void kernel_launch(void* const* d_in, const int* in_sizes, int n_in,
                              void* d_out, int out_size)
{
    const float* h   = (const float*)d_in[0];
    const float* pos = (const float*)d_in[1];
    const int*   ei  = (const int*)d_in[2];
    const float* We1 = (const float*)d_in[3];
    const float* be1 = (const float*)d_in[4];
    const float* We2 = (const float*)d_in[5];
    const float* be2 = (const float*)d_in[6];
    const float* Wn1 = (const float*)d_in[7];
    const float* bn1 = (const float*)d_in[8];
    const float* Wn2 = (const float*)d_in[9];
    const float* bn2 = (const float*)d_in[10];
    const float* Wc1 = (const float*)d_in[11];
    const float* bc1 = (const float*)d_in[12];
    const float* Wc2 = (const float*)d_in[13];

    const int N = in_sizes[0] / DD;
    const long long E = (long long)in_sizes[2] / 2;

    float* h_out   = (float*)d_out;
    float* pos_out = h_out + (long long)N * DD;

    cudaFuncSetAttribute(egnn_edge_mma, cudaFuncAttributeMaxDynamicSharedMemorySize, EDGE_SMEM_BYTES);
    cudaFuncSetAttribute(egnn_node_kernel, cudaFuncAttributeMaxDynamicSharedMemorySize, NODE_SMEM_BYTES);

    egnn_detect_kernel<<<1, 1>>>(ei);
    egnn_prep_kernel<<<(8 * 8192 + 255) / 256, 256>>>(We1, We2, Wc1);

    long long nAgg = (long long)N * DD;
    long long nPos = (long long)N * 3;
    int ib = (int)((nAgg + 255) / 256);
    egnn_init_kernel<<<ib, 256>>>(pos, pos_out, nAgg, nPos);

    int eb = (int)((E + EPB - 1) / EPB);
    egnn_edge_mma<<<eb, 256, EDGE_SMEM_BYTES>>>(
        h, pos, ei, E, We1, be1, be2, bc1, Wc2, pos_out);

    int nb = (N + TE - 1) / TE;
    egnn_node_kernel<<<nb, 256, NODE_SMEM_BYTES>>>(
        h, Wn1, bn1, Wn2, bn2, h_out, N);
}